// round 8
// baseline (speedup 1.0000x reference)
#include <cuda_runtime.h>
#include <cstdint>

namespace {

constexpr int Bn = 32768;
constexpr int Nn = 512;
constexpr int Fn = 8;
constexpr int On = 32;
constexpr int T  = 128;
constexpr int NBLK = 912;                      // 152 SMs x 6 resident blocks

constexpr unsigned NEIGH_BYTES = Nn * Fn * 4;  // 16384
constexpr unsigned MASK_BYTES  = Nn * 4;       // 2048

__device__ __forceinline__ uint32_t s2u(const void* p) {
    uint32_t a;
    asm("{ .reg .u64 t; cvta.to.shared.u64 t, %1; cvt.u32.u64 %0, t; }"
        : "=r"(a) : "l"(p));
    return a;
}

__device__ __forceinline__ void wait_parity(uint32_t mb, uint32_t ph) {
    uint32_t done;
    asm volatile(
        "{\n\t.reg .pred p;\n\t"
        "mbarrier.try_wait.parity.acquire.cta.shared::cta.b64 p, [%1], %2;\n\t"
        "selp.b32 %0, 1, 0, p;\n\t}"
        : "=r"(done) : "r"(mb), "r"(ph) : "memory");
    if (!done) {
        asm volatile(
            "{\n\t.reg .pred P1;\n\t"
            "W_%=:\n\t"
            "mbarrier.try_wait.parity.acquire.cta.shared::cta.b64 P1, [%0], %1, 0x989680;\n\t"
            "@P1 bra.uni D_%=;\n\t"
            "bra.uni W_%=;\n\t"
            "D_%=:\n\t}"
            :: "r"(mb), "r"(ph) : "memory");
    }
}

__global__ __launch_bounds__(T)
void gat_kernel(const float* __restrict__ ego,          // [B, F]
                const float* __restrict__ neigh,        // [B, N, F]
                const int*   __restrict__ mask,         // [B, N] int32
                const float* __restrict__ W_ego,        // [F, F]
                const float* __restrict__ b_ego,        // [F]
                const float* __restrict__ w_attn,       // [2F]
                const float* __restrict__ b_attn,       // [1]
                const float* __restrict__ W_out,        // [F, OUT]
                const float* __restrict__ b_out,        // [OUT]
                float* __restrict__ out)                // [B, OUT]
{
    __shared__ alignas(128) float s_n[2][Nn * Fn];      // 2 x 16 KB
    __shared__ alignas(128) int   s_m[2][Nn];           // 2 x 2 KB
    __shared__ alignas(8) uint64_t mbar[2];
    __shared__ float s_max[4], s_sum[4], s_part[4][Fn], s_tb, s_agg[Fn];

    const int t    = threadIdx.x;
    const int warp = t >> 5;
    const int lane = t & 31;
    const int b0   = blockIdx.x;
    const int nrows = (Bn - b0 + NBLK - 1) / NBLK;

    if (t == 0) {
        asm volatile("mbarrier.init.shared.b64 [%0], 1;" :: "r"(s2u(&mbar[0])) : "memory");
        asm volatile("mbarrier.init.shared.b64 [%0], 1;" :: "r"(s2u(&mbar[1])) : "memory");
    }
    __syncthreads();

    // ---- TMA issue for local row i (t==0 only).
    auto issue = [&](int i) {
        const size_t b = (size_t)b0 + (size_t)i * NBLK;
        const int s = i & 1;
        const uint32_t mb = s2u(&mbar[s]);
        asm volatile("mbarrier.arrive.expect_tx.shared.b64 _, [%0], %1;"
                     :: "r"(mb), "r"(NEIGH_BYTES + MASK_BYTES) : "memory");
        asm volatile("cp.async.bulk.shared::cta.global.mbarrier::complete_tx::bytes "
                     "[%0], [%1], %2, [%3];"
                     :: "r"(s2u(s_n[s])), "l"(neigh + b * (Nn * Fn)),
                        "r"(NEIGH_BYTES), "r"(mb) : "memory");
        asm volatile("cp.async.bulk.shared::cta.global.mbarrier::complete_tx::bytes "
                     "[%0], [%1], %2, [%3];"
                     :: "r"(s2u(s_m[s])), "l"(mask + b * Nn),
                        "r"(MASK_BYTES), "r"(mb) : "memory");
    };

    if (t == 0) {
        if (nrows > 0) issue(0);
        if (nrows > 1) issue(1);
    }

    // wa_n in registers; half-row weight selection is constant per thread (t&1).
    const int half = t & 1;
    const float wa = w_attn[Fn + half * 4 + 0];
    const float wb = w_attn[Fn + half * 4 + 1];
    const float wc = w_attn[Fn + half * 4 + 2];
    const float wd = w_attn[Fn + half * 4 + 3];

    for (int i = 0; i < nrows; i++) {
        const size_t b = (size_t)b0 + (size_t)i * NBLK;
        const int s = i & 1;
        const uint32_t ph = (i >> 1) & 1;

        // ---- Ego scalar for this row (overlapped with TMA wait).
        if (t == 0) {
            float tb = b_attn[0];
#pragma unroll
            for (int j = 0; j < Fn; j++) {
                float p = b_ego[j];
#pragma unroll
                for (int k = 0; k < Fn; k++)
                    p += ego[b * Fn + k] * W_ego[k * Fn + j];
                tb += p * w_attn[j];
            }
            s_tb = tb;
        }

        wait_parity(s2u(&mbar[s]), ph);
        __syncthreads();                 // data visible to all; s_tb ordered
        const float tb = s_tb;

        const float4* sn4 = reinterpret_cast<const float4*>(s_n[s]);
        constexpr float NEG = -1e9f;

        // ---- Pass 1: half-row scores. Lane stride 16B -> conflict-free LDS.128.
        // Thread t handles half #(t&1) of rows r = (t>>1) + j*64.
        float sc[8];
        float mx = NEG;
#pragma unroll
        for (int j = 0; j < 8; j++) {
            const int q = t + j * T;         // half-row index
            const int r = (t >> 1) + j * 64; // row index
            const float4 v = sn4[q];
            float p = v.x * wa + v.y * wb + v.z * wc + v.w * wd;
            p += __shfl_xor_sync(0xffffffffu, p, 1);   // combine halves
            float scj = tb + p;
            scj = s_m[s][r] ? scj : NEG;
            sc[j] = scj;
            mx = fmaxf(mx, scj);
        }
#pragma unroll
        for (int o = 16; o; o >>= 1)
            mx = fmaxf(mx, __shfl_xor_sync(0xffffffffu, mx, o));
        if (lane == 0) s_max[warp] = mx;
        __syncthreads();
        mx = fmaxf(fmaxf(s_max[0], s_max[1]), fmaxf(s_max[2], s_max[3]));

        // ---- exp + sum (each row counted once: even lanes only).
        float e[8];
        float sum = 0.f;
#pragma unroll
        for (int j = 0; j < 8; j++) {
            e[j] = (sc[j] > -5e8f) ? __expf(sc[j] - mx) : 0.f;
            if (half == 0) sum += e[j];
        }
#pragma unroll
        for (int o = 16; o; o >>= 1)
            sum += __shfl_xor_sync(0xffffffffu, sum, o);
        if (lane == 0) s_sum[warp] = sum;

        // ---- Pass 2: weighted aggregation over my 4 features.
        float a0 = 0.f, a1 = 0.f, a2 = 0.f, a3 = 0.f;
#pragma unroll
        for (int j = 0; j < 8; j++) {
            const float4 v = sn4[t + j * T];
            const float ek = e[j];
            a0 += ek * v.x; a1 += ek * v.y; a2 += ek * v.z; a3 += ek * v.w;
        }
        __syncthreads();                 // all smem reads of stage s complete
        if (t == 0 && i + 2 < nrows) issue(i + 2);   // keep DRAM streaming

        // Parity-preserving butterfly: even lanes reduce feats 0-3, odd 4-7.
#pragma unroll
        for (int o = 16; o >= 2; o >>= 1) {
            a0 += __shfl_xor_sync(0xffffffffu, a0, o);
            a1 += __shfl_xor_sync(0xffffffffu, a1, o);
            a2 += __shfl_xor_sync(0xffffffffu, a2, o);
            a3 += __shfl_xor_sync(0xffffffffu, a3, o);
        }
        if (lane < 2) {
            s_part[warp][half * 4 + 0] = a0;
            s_part[warp][half * 4 + 1] = a1;
            s_part[warp][half * 4 + 2] = a2;
            s_part[warp][half * 4 + 3] = a3;
        }
        __syncthreads();

        // ---- Normalize (all-masked: tot==0 -> agg=0 -> out=b_out).
        if (t < Fn) {
            const float tot = s_sum[0] + s_sum[1] + s_sum[2] + s_sum[3];
            const float rinv = (tot > 0.f) ? (1.f / tot) : 0.f;
            s_agg[t] = (s_part[0][t] + s_part[1][t] + s_part[2][t] + s_part[3][t]) * rinv;
        }
        __syncthreads();

        // ---- Output GEMV.
        if (t < On) {
            float v = b_out[t];
#pragma unroll
            for (int f = 0; f < Fn; f++)
                v += s_agg[f] * W_out[f * On + t];
            out[b * On + t] = v;
        }
        // next iteration's wait + sync orders reuse of s_agg/s_part/s_tb
    }
}

} // namespace

extern "C" void kernel_launch(void* const* d_in, const int* in_sizes, int n_in,
                              void* d_out, int out_size)
{
    const float* ego    = (const float*)d_in[0];
    const float* neigh  = (const float*)d_in[1];
    const int*   mask   = (const int*)d_in[2];
    const float* W_ego  = (const float*)d_in[3];
    const float* b_ego  = (const float*)d_in[4];
    const float* w_attn = (const float*)d_in[5];
    const float* b_attn = (const float*)d_in[6];
    const float* W_out  = (const float*)d_in[7];
    const float* b_out  = (const float*)d_in[8];
    float*       out    = (float*)d_out;

    gat_kernel<<<NBLK, T>>>(ego, neigh, mask, W_ego, b_ego, w_attn, b_attn,
                            W_out, b_out, out);
}